// round 1
// baseline (speedup 1.0000x reference)
#include <cuda_runtime.h>
#include <cstdint>

#define BLOCK 256
#define GRID  1184   // 148 SMs * 8 blocks

__device__ float g_partials[GRID];

__global__ __launch_bounds__(BLOCK) void deadzone_partial_kernel(
    const float* __restrict__ inputs,
    const float* __restrict__ targets,
    int n)
{
    const float ERROR_OK = 0.1f;
    float acc = 0.0f;

    // vectorized main loop: float4 per array per step
    int n4 = n >> 2;  // number of float4
    const float4* in4 = reinterpret_cast<const float4*>(inputs);
    const float4* tg4 = reinterpret_cast<const float4*>(targets);

    int tid = blockIdx.x * BLOCK + threadIdx.x;
    int stride = GRID * BLOCK;

    for (int i = tid; i < n4; i += stride) {
        float4 a = in4[i];
        float4 b = tg4[i];
        float d0 = a.x - b.x;
        float d1 = a.y - b.y;
        float d2 = a.z - b.z;
        float d3 = a.w - b.w;
        // dead-zone: zero if |d| < ERROR_OK
        d0 = (fabsf(d0) < ERROR_OK) ? 0.0f : d0;
        d1 = (fabsf(d1) < ERROR_OK) ? 0.0f : d1;
        d2 = (fabsf(d2) < ERROR_OK) ? 0.0f : d2;
        d3 = (fabsf(d3) < ERROR_OK) ? 0.0f : d3;
        acc = fmaf(d0, d0, acc);
        acc = fmaf(d1, d1, acc);
        acc = fmaf(d2, d2, acc);
        acc = fmaf(d3, d3, acc);
    }

    // tail (n not multiple of 4) — N=33554432 is, but stay general
    for (int i = (n4 << 2) + tid; i < n; i += stride) {
        float d = inputs[i] - targets[i];
        d = (fabsf(d) < ERROR_OK) ? 0.0f : d;
        acc = fmaf(d, d, acc);
    }

    // warp reduction
    #pragma unroll
    for (int off = 16; off > 0; off >>= 1)
        acc += __shfl_down_sync(0xFFFFFFFFu, acc, off);

    __shared__ float warp_sums[BLOCK / 32];
    int lane = threadIdx.x & 31;
    int wid  = threadIdx.x >> 5;
    if (lane == 0) warp_sums[wid] = acc;
    __syncthreads();

    if (wid == 0) {
        float v = (lane < BLOCK / 32) ? warp_sums[lane] : 0.0f;
        #pragma unroll
        for (int off = 16; off > 0; off >>= 1)
            v += __shfl_down_sync(0xFFFFFFFFu, v, off);
        if (lane == 0) g_partials[blockIdx.x] = v;
    }
}

__global__ __launch_bounds__(1024) void deadzone_final_kernel(float* __restrict__ out, float inv_n)
{
    float acc = 0.0f;
    for (int i = threadIdx.x; i < GRID; i += 1024)
        acc += g_partials[i];

    #pragma unroll
    for (int off = 16; off > 0; off >>= 1)
        acc += __shfl_down_sync(0xFFFFFFFFu, acc, off);

    __shared__ float warp_sums[32];
    int lane = threadIdx.x & 31;
    int wid  = threadIdx.x >> 5;
    if (lane == 0) warp_sums[wid] = acc;
    __syncthreads();

    if (wid == 0) {
        float v = (lane < 32) ? warp_sums[lane] : 0.0f;
        #pragma unroll
        for (int off = 16; off > 0; off >>= 1)
            v += __shfl_down_sync(0xFFFFFFFFu, v, off);
        if (lane == 0) out[0] = v * inv_n;
    }
}

extern "C" void kernel_launch(void* const* d_in, const int* in_sizes, int n_in,
                              void* d_out, int out_size)
{
    const float* inputs  = (const float*)d_in[0];
    const float* targets = (const float*)d_in[1];
    float* out = (float*)d_out;
    int n = in_sizes[0];

    deadzone_partial_kernel<<<GRID, BLOCK>>>(inputs, targets, n);
    deadzone_final_kernel<<<1, 1024>>>(out, 1.0f / (float)n);
}